// round 16
// baseline (speedup 1.0000x reference)
#include <cuda_runtime.h>
#include <cstdint>

#define T_LEN 1024
#define B_SZ  64
#define D_DIM 512
#define N_TAG 24

// Output layout (float32): decoded | pot | lens | trans
#define OFF_POT   (B_SZ * T_LEN)                     // 65536
#define OFF_LENS  (OFF_POT + B_SZ * T_LEN * N_TAG)   // 1638400
#define OFF_TRANS (OFF_LENS + B_SZ)                  // 1638464

typedef unsigned long long u64;

__device__ int g_flags[256];   // tile-ready flags, s = j*64 + b

// Packed f32x2 ops (sm_103a — PTX only)
__device__ __forceinline__ u64 ffma2(u64 a, u64 b, u64 c) {
    u64 d;
    asm("fma.rn.f32x2 %0, %1, %2, %3;" : "=l"(d) : "l"(a), "l"(b), "l"(c));
    return d;
}
__device__ __forceinline__ u64 fadd2(u64 a, u64 b) {
    u64 d;
    asm("add.rn.f32x2 %0, %1, %2;" : "=l"(d) : "l"(a), "l"(b));
    return d;
}
__device__ __forceinline__ float lof(u64 v) {
    return __uint_as_float((unsigned)(v & 0xffffffffull));
}
__device__ __forceinline__ float hif(u64 v) {
    return __uint_as_float((unsigned)(v >> 32));
}

struct __align__(16) f4u { u64 lo, hi; };

__device__ __forceinline__ void cpasync16(uint32_t s, const void* g) {
    asm volatile("cp.async.cg.shared.global [%0], [%1], 16;" :: "r"(s), "l"(g));
}
__device__ __forceinline__ void cpcommit() {
    asm volatile("cp.async.commit_group;");
}
template <int N> __device__ __forceinline__ void cpwait() {
    asm volatile("cp.async.wait_group %0;" :: "n"(N));
}
__device__ __forceinline__ void bar96() {
    asm volatile("bar.sync 1, 96;" ::: "memory");
}

// GEMM tiling constants (R11/R14 proven)
#define KT       16
#define NKT      (D_DIM / KT)    // 32
#define XS_STRIDE 10             // u64 per row: 64B data + 16B pad
#define XS_U64   (256 * XS_STRIDE)
#define WTAG_F4U (D_DIM / 4)
#define ROWS_BLK 256
#define GEMM_SMEM ((N_TAG * (D_DIM / 2) + 2 * XS_U64) * 8)   // 90112

// Viterbi constants
#define CHUNK 64
#define NCHUNK (T_LEN / CHUNK)          // 16
#define CH_FLOATS (CHUNK * N_TAG)       // 1536 floats = 6144 B
#define BANK 16
#define NBANK (T_LEN / BANK)            // 64
#define VS_POT    0
#define VS_RING   12288
#define VS_BP     20480
#define VS_CMAP   53248
#define VS_EARR   54784
#define VS_LTAG   54848

extern __shared__ char fused_smem[];

// ---------------------------------------------------------------------------
// GEMM path (blocks 64..319): tile s = j*64 + b covers rows
// [b*1024 + j*256, +256). Math identical to R14 (pot bitwise unchanged);
// only the block->tile mapping is chunk-major so early chunks land first.
// ---------------------------------------------------------------------------
__device__ void gemm_path(int s,
                          const float* __restrict__ x,
                          const float* __restrict__ W,
                          const float* __restrict__ bias,
                          const float* __restrict__ lb,
                          const float* __restrict__ rb,
                          float* __restrict__ potOut) {
    u64* dyn = (u64*)fused_smem;
    u64* Ws  = dyn;
    u64* xs0 = dyn + N_TAG * (D_DIM / 2);
    u64* xs1 = xs0 + XS_U64;
    float* Wsf = (float*)Ws;

    int tid = threadIdx.x;

    for (int i = tid; i < D_DIM * N_TAG; i += 256) {
        int k = i / N_TAG;
        int n = i - k * N_TAG;
        Wsf[n * D_DIM + k] = W[i];
    }

    int rid = tid & 63;
    int h   = tid >> 6;
    int bb_ = s & 63;            // batch
    int jj_ = s >> 6;            // quarter within batch
    int rowg = bb_ * T_LEN + jj_ * ROWS_BLK;

    const float4* x4g = (const float4*)x + (size_t)rowg * (D_DIM / 4);

    uint32_t xsa0 = (uint32_t)__cvta_generic_to_shared(xs0);
    uint32_t xsa1 = (uint32_t)__cvta_generic_to_shared(xs1);

#pragma unroll
    for (int j = 0; j < 4; j++) {
        int idx = tid + j * 256;
        int row = idx >> 2;
        int c   = idx & 3;
        cpasync16(xsa0 + row * 80 + c * 16,
                  x4g + (size_t)row * (D_DIM / 4) + 0 * 4 + c);
    }
    cpcommit();
#pragma unroll
    for (int j = 0; j < 4; j++) {
        int idx = tid + j * 256;
        int row = idx >> 2;
        int c   = idx & 3;
        cpasync16(xsa1 + row * 80 + c * 16,
                  x4g + (size_t)row * (D_DIM / 4) + 1 * 4 + c);
    }
    cpcommit();

    u64 acc[4][6];
#pragma unroll
    for (int j = 0; j < 4; j++)
#pragma unroll
        for (int i = 0; i < 6; i++) acc[j][i] = 0ull;

    const f4u* wb = (const f4u*)(Ws + (h * 6) * (D_DIM / 2));

    for (int kt = 0; kt < NKT; kt++) {
        cpwait<1>();
        __syncthreads();

        u64* xs = (kt & 1) ? xs1 : xs0;
        const f4u* xrow0 = (const f4u*)(xs + (rid)       * XS_STRIDE);
        const f4u* xrow1 = (const f4u*)(xs + (rid + 64)  * XS_STRIDE);
        const f4u* xrow2 = (const f4u*)(xs + (rid + 128) * XS_STRIDE);
        const f4u* xrow3 = (const f4u*)(xs + (rid + 192) * XS_STRIDE);

#pragma unroll
        for (int kk2 = 0; kk2 < KT / 4; kk2++) {
            f4u xv0 = xrow0[kk2];
            f4u xv1 = xrow1[kk2];
            f4u xv2 = xrow2[kk2];
            f4u xv3 = xrow3[kk2];
#pragma unroll
            for (int i = 0; i < 6; i++) {
                f4u wv = wb[i * WTAG_F4U + kt * (KT / 4) + kk2];
                acc[0][i] = ffma2(xv0.lo, wv.lo, acc[0][i]);
                acc[0][i] = ffma2(xv0.hi, wv.hi, acc[0][i]);
                acc[1][i] = ffma2(xv1.lo, wv.lo, acc[1][i]);
                acc[1][i] = ffma2(xv1.hi, wv.hi, acc[1][i]);
                acc[2][i] = ffma2(xv2.lo, wv.lo, acc[2][i]);
                acc[2][i] = ffma2(xv2.hi, wv.hi, acc[2][i]);
                acc[3][i] = ffma2(xv3.lo, wv.lo, acc[3][i]);
                acc[3][i] = ffma2(xv3.hi, wv.hi, acc[3][i]);
            }
        }

        __syncthreads();
        if (kt + 2 < NKT) {
            uint32_t dst = (kt & 1) ? xsa1 : xsa0;
#pragma unroll
            for (int j = 0; j < 4; j++) {
                int idx = tid + j * 256;
                int row = idx >> 2;
                int c   = idx & 3;
                cpasync16(dst + row * 80 + c * 16,
                          x4g + (size_t)row * (D_DIM / 4) + (kt + 2) * 4 + c);
            }
            cpcommit();
        }
    }

    float bb[6], lbb[6], rbb[6];
#pragma unroll
    for (int i = 0; i < 6; i++) {
        int n = h * 6 + i;
        bb[i]  = bias[n];
        lbb[i] = lb[n];
        rbb[i] = rb[n];
    }
#pragma unroll
    for (int j = 0; j < 4; j++) {
        int r = rowg + rid + j * 64;
        int t = r & (T_LEN - 1);
        float v[6];
#pragma unroll
        for (int i = 0; i < 6; i++) {
            float sv = lof(acc[j][i]) + hif(acc[j][i]) + bb[i];
            if (t == 0)         sv += lbb[i];
            if (t == T_LEN - 1) sv += rbb[i];
            v[i] = sv;
        }
        float2* outp = (float2*)(potOut + (size_t)r * N_TAG + h * 6);
        outp[0] = make_float2(v[0], v[1]);
        outp[1] = make_float2(v[2], v[3]);
        outp[2] = make_float2(v[4], v[5]);
    }

    // Publish tile: fence each thread's stores, then set flag.
    __threadfence();
    __syncthreads();
    if (tid == 0) atomicExch(&g_flags[s], 1);
}

// ---------------------------------------------------------------------------
// Viterbi path (blocks 0..63): R14/R15 warp-specialized forward + parallel
// backtrace, with per-tile spin-waits on the GEMM producer flags.
// ---------------------------------------------------------------------------
__device__ void viterbi_path(int b,
                             const float* __restrict__ pot,
                             const float* __restrict__ trans,
                             float* __restrict__ decodedOut) {
    float* potS = (float*)(fused_smem + VS_POT);
    float* ring = (float*)(fused_smem + VS_RING);
    unsigned char* bp_s = (unsigned char*)(fused_smem + VS_BP);
    unsigned char* cMap = (unsigned char*)(fused_smem + VS_CMAP);
    unsigned char* eArr = (unsigned char*)(fused_smem + VS_EARR);
    int* lastTagS = (int*)(fused_smem + VS_LTAG);

    int tid  = threadIdx.x;
    if (tid >= 128) return;     // warps 4-7 unused
    int wid  = tid >> 5;
    int lane = tid & 31;
    int ln   = lane < N_TAG ? lane : (N_TAG - 1);

    if (wid == 3) return;       // spare warp (not in bar96 count)

    const float* potB = pot + (size_t)b * T_LEN * N_TAG;

    if (wid == 2) bp_s[0 * 32 + lane] = (unsigned char)ln;   // identity row t=0

    u64 tc2[12];
#pragma unroll
    for (int j = 0; j < 12; j++) {
        float t0 = trans[(2 * j) * N_TAG + ln];
        float t1 = trans[(2 * j + 1) * N_TAG + ln];
        tc2[j] = (u64)__float_as_uint(t0) | ((u64)__float_as_uint(t1) << 32);
    }

    if (wid == 0) {
        // ------------------- A: value warp -------------------
        uint32_t potS_addr = (uint32_t)__cvta_generic_to_shared(potS);

        // wait for tile (b, j): flag index j*64 + b
#define WAIT_TILE(jj) { if (lane == 0) {                                   \
                            while (atomicAdd(&g_flags[(jj) * 64 + b], 0) == 0) \
                                __nanosleep(128);                          \
                        } __syncwarp(); }

        WAIT_TILE(0);   // chunks 0..3 live in tile j=0

        // Prologue: chunks 0 and 1
#pragma unroll
        for (int j = 0; j < 12; j++)
            cpasync16(potS_addr + j * 512 + lane * 16, potB + j * 128 + lane * 4);
        cpcommit();
#pragma unroll
        for (int j = 0; j < 12; j++)
            cpasync16(potS_addr + 6144 + j * 512 + lane * 16,
                      potB + CH_FLOATS + j * 128 + lane * 4);
        cpcommit();
        cpwait<1>();
        __syncwarp();

        float alpha = potS[ln];         // t = 0
        ring[0 * 32 + lane] = alpha;    // slot 0
        __syncwarp();

        for (int k = 0; k < NBANK; k++) {
            int tstart = (k == 0) ? 1 : 16 * k;
            int tend   = 16 * k + 16;
#pragma unroll 4
            for (int t = tstart; t < tend; t++) {
                float pcur = potS[((t >> 6) & 1) * CH_FLOATS
                                  + (t & 63) * N_TAG + ln];

                const f4u* ap = (const f4u*)(ring + ((t - 1) & 63) * 32);
                float s[N_TAG];
#pragma unroll
                for (int q = 0; q < 6; q++) {
                    f4u a = ap[q];
                    u64 sa = fadd2(a.lo, tc2[2 * q]);
                    u64 sb = fadd2(a.hi, tc2[2 * q + 1]);
                    s[4 * q + 0] = lof(sa); s[4 * q + 1] = hif(sa);
                    s[4 * q + 2] = lof(sb); s[4 * q + 3] = hif(sb);
                }
#pragma unroll
                for (int st = 1; st < N_TAG; st <<= 1) {
#pragma unroll
                    for (int i = 0; i + st < N_TAG; i += 2 * st)
                        s[i] = fmaxf(s[i], s[i + st]);
                }
                alpha = s[0] + pcur;
                ring[(t & 63) * 32 + lane] = alpha;
                __syncwarp();
            }
            // end of chunk c = k>>2: refill c+2 (after its tile is ready),
            // then ensure chunk c+1 landed.
            if ((k & 3) == 3) {
                int c = k >> 2;
                if (c + 2 < NCHUNK) {
                    WAIT_TILE((c + 2) >> 2);
                    uint32_t dst = potS_addr + (c & 1) * 6144;
                    const float* src = potB + (size_t)(c + 2) * CH_FLOATS;
#pragma unroll
                    for (int j = 0; j < 12; j++)
                        cpasync16(dst + j * 512 + lane * 16,
                                  src + j * 128 + lane * 4);
                    cpcommit();
                    cpwait<1>();
                } else {
                    cpwait<0>();
                }
                __syncwarp();
            }
            bar96();    // release bank k to bp warps
        }
#undef WAIT_TILE

        // last_tag = first-occurrence argmax over lanes 0..23
        float bv = __shfl_sync(0xffffffffu, alpha, 0);
        int   bt = 0;
#pragma unroll
        for (int m = 1; m < N_TAG; m++) {
            float v = __shfl_sync(0xffffffffu, alpha, m);
            if (v > bv) { bv = v; bt = m; }
        }
        if (lane == 0) lastTagS[0] = bt;
        bar96();        // bp warps finished last bank; lastTag visible
    } else {
        // ------------------- B0/B1: backpointer warps -------------------
        int w = wid - 1;
        for (int k = 0; k < NBANK; k++) {
            bar96();        // bank k alphas ready
            int tstart = ((k == 0) ? 1 : 16 * k) + w;
            int tend   = 16 * k + 16;
            for (int t = tstart; t < tend; t += 2) {
                const f4u* ap = (const f4u*)(ring + ((t - 1) & 63) * 32);
                float s[N_TAG];
                int   idx[N_TAG];
#pragma unroll
                for (int q = 0; q < 6; q++) {
                    f4u a = ap[q];
                    u64 sa = fadd2(a.lo, tc2[2 * q]);
                    u64 sb = fadd2(a.hi, tc2[2 * q + 1]);
                    s[4 * q + 0] = lof(sa); s[4 * q + 1] = hif(sa);
                    s[4 * q + 2] = lof(sb); s[4 * q + 3] = hif(sb);
                }
#pragma unroll
                for (int m = 0; m < N_TAG; m++) idx[m] = m;

#define VCMP(i, j) { bool g = s[j] > s[i];          \
                     idx[i] = g ? idx[j] : idx[i];   \
                     s[i] = fmaxf(s[i], s[j]); }
#pragma unroll
                for (int st = 1; st < N_TAG; st <<= 1) {
#pragma unroll
                    for (int i = 0; i + st < N_TAG; i += 2 * st) VCMP(i, i + st)
                }
#undef VCMP
                bp_s[t * 32 + lane] = (unsigned char)idx[0];
            }
        }
        bar96();
    }

    // =============== Parallel backtrace (96 threads) ===============
    int tt = wid * 32 + lane;

    // Phase 1: per-bank composed maps (16 chains/thread, ILP)
    {
        int xReg[16];
        int bankT[16];
#pragma unroll
        for (int j = 0; j < 16; j++) {
            int p = tt + 96 * j;
            bankT[j] = (p / 24) * 16;
            xReg[j] = p % 24;
        }
        for (int i = 15; i >= 0; i--) {
#pragma unroll
            for (int j = 0; j < 16; j++)
                xReg[j] = bp_s[(bankT[j] + i) * 32 + xReg[j]];
        }
#pragma unroll
        for (int j = 0; j < 16; j++)
            cMap[tt + 96 * j] = (unsigned char)xReg[j];
    }
    bar96();

    // Phase 2: boundary tags
    if (tt == 0) {
        int e = lastTagS[0];
        eArr[63] = (unsigned char)e;
        for (int k = 63; k >= 1; k--) {
            e = cMap[k * 24 + e];
            eArr[k - 1] = (unsigned char)e;
        }
    }
    bar96();

    // Phase 3: reconstruct decoded per bank
    if (tt < 64) {
        int k = tt;
        int xx = eArr[k];
        float* dec = decodedOut + (size_t)b * T_LEN;
        if (k == 63) dec[1023] = (float)xx;
        for (int t = 16 * k + 15; t >= 16 * k; t--) {
            xx = bp_s[t * 32 + xx];
            if (t > 0) dec[t - 1] = (float)xx;
        }
    }
}

// ---------------------------------------------------------------------------
// Fused kernel: blocks 0..63 viterbi (scheduled first), 64..319 GEMM tiles.
// ---------------------------------------------------------------------------
__global__ void __launch_bounds__(256, 2)
fused_kernel(const float* __restrict__ x,
             const float* __restrict__ W,
             const float* __restrict__ bias,
             const float* __restrict__ lb,
             const float* __restrict__ rb,
             const float* __restrict__ trans,
             float* __restrict__ out) {
    if (blockIdx.x >= 64)
        gemm_path(blockIdx.x - 64, x, W, bias, lb, rb, out + OFF_POT);
    else
        viterbi_path(blockIdx.x, out + OFF_POT, trans, out);
}

// ---------------------------------------------------------------------------
// Pre-kernel: zero flags, fill lens, copy trans.
// ---------------------------------------------------------------------------
__global__ void pre_kernel(const float* __restrict__ trans,
                           float* __restrict__ out) {
    int i = threadIdx.x;
    if (i < 256)           g_flags[i] = 0;
    if (i < B_SZ)          out[OFF_LENS + i]  = (float)T_LEN;
    if (i < N_TAG * N_TAG) out[OFF_TRANS + i] = trans[i];
}

// ---------------------------------------------------------------------------
extern "C" void kernel_launch(void* const* d_in, const int* in_sizes, int n_in,
                              void* d_out, int out_size) {
    const float* x     = (const float*)d_in[0];
    const float* W     = (const float*)d_in[1];
    const float* bias  = (const float*)d_in[2];
    const float* trans = (const float*)d_in[3];
    const float* lb    = (const float*)d_in[4];
    const float* rb    = (const float*)d_in[5];

    float* out = (float*)d_out;

    cudaFuncSetAttribute(fused_kernel,
                         cudaFuncAttributeMaxDynamicSharedMemorySize, GEMM_SMEM);

    pre_kernel<<<1, 640>>>(trans, out);
    fused_kernel<<<320, 256, GEMM_SMEM>>>(x, W, bias, lb, rb, trans, out);
}

// round 17
// speedup vs baseline: 1.0435x; 1.0435x over previous
#include <cuda_runtime.h>
#include <cstdint>

#define T_LEN 1024
#define B_SZ  64
#define D_DIM 512
#define N_TAG 24

// Output layout (float32): decoded | pot | lens | trans
#define OFF_POT   (B_SZ * T_LEN)                     // 65536
#define OFF_LENS  (OFF_POT + B_SZ * T_LEN * N_TAG)   // 1638400
#define OFF_TRANS (OFF_LENS + B_SZ)                  // 1638464

typedef unsigned long long u64;

// Packed f32x2 ops (sm_103a — PTX only)
__device__ __forceinline__ u64 ffma2(u64 a, u64 b, u64 c) {
    u64 d;
    asm("fma.rn.f32x2 %0, %1, %2, %3;" : "=l"(d) : "l"(a), "l"(b), "l"(c));
    return d;
}
__device__ __forceinline__ u64 fadd2(u64 a, u64 b) {
    u64 d;
    asm("add.rn.f32x2 %0, %1, %2;" : "=l"(d) : "l"(a), "l"(b));
    return d;
}
__device__ __forceinline__ float lof(u64 v) {
    return __uint_as_float((unsigned)(v & 0xffffffffull));
}
__device__ __forceinline__ float hif(u64 v) {
    return __uint_as_float((unsigned)(v >> 32));
}

struct __align__(16) f4u { u64 lo, hi; };

__device__ __forceinline__ void cpasync16(uint32_t s, const void* g) {
    asm volatile("cp.async.cg.shared.global [%0], [%1], 16;" :: "r"(s), "l"(g));
}
__device__ __forceinline__ void cpcommit() {
    asm volatile("cp.async.commit_group;");
}
template <int N> __device__ __forceinline__ void cpwait() {
    asm volatile("cp.async.wait_group %0;" :: "n"(N));
}
__device__ __forceinline__ void bar96() {
    asm volatile("bar.sync 1, 96;" ::: "memory");
}

// ---------------------------------------------------------------------------
// GEMM (R11/R14 proven — DO NOT TOUCH): 256 threads, 256 rows/block, grid 256.
// Thread: 4 rows x 6 tags. x via cp.async double-buffered tiles (KT=16).
// ---------------------------------------------------------------------------
#define KT       16
#define NKT      (D_DIM / KT)    // 32
#define XS_STRIDE 10             // u64 per row: 64B data + 16B pad
#define XS_U64   (256 * XS_STRIDE)
#define WTAG_F4U (D_DIM / 4)
#define ROWS_BLK 256

extern __shared__ u64 dyn_smem[];

__global__ void __launch_bounds__(256, 2)
gemm_pot_kernel(const float* __restrict__ x,
                const float* __restrict__ W,
                const float* __restrict__ bias,
                const float* __restrict__ lb,
                const float* __restrict__ rb,
                float* __restrict__ potOut) {
    u64* Ws = dyn_smem;
    u64* xs0 = dyn_smem + N_TAG * (D_DIM / 2);
    u64* xs1 = xs0 + XS_U64;
    float* Wsf = (float*)Ws;

    int tid = threadIdx.x;

    for (int i = tid; i < D_DIM * N_TAG; i += 256) {
        int k = i / N_TAG;
        int n = i - k * N_TAG;
        Wsf[n * D_DIM + k] = W[i];
    }

    int rid = tid & 63;
    int h   = tid >> 6;
    int rowg = blockIdx.x * ROWS_BLK;

    const float4* x4g = (const float4*)x + (size_t)rowg * (D_DIM / 4);

    uint32_t xsa0 = (uint32_t)__cvta_generic_to_shared(xs0);
    uint32_t xsa1 = (uint32_t)__cvta_generic_to_shared(xs1);

#pragma unroll
    for (int j = 0; j < 4; j++) {
        int idx = tid + j * 256;
        int row = idx >> 2;
        int c   = idx & 3;
        cpasync16(xsa0 + row * 80 + c * 16,
                  x4g + (size_t)row * (D_DIM / 4) + 0 * 4 + c);
    }
    cpcommit();
#pragma unroll
    for (int j = 0; j < 4; j++) {
        int idx = tid + j * 256;
        int row = idx >> 2;
        int c   = idx & 3;
        cpasync16(xsa1 + row * 80 + c * 16,
                  x4g + (size_t)row * (D_DIM / 4) + 1 * 4 + c);
    }
    cpcommit();

    u64 acc[4][6];
#pragma unroll
    for (int j = 0; j < 4; j++)
#pragma unroll
        for (int i = 0; i < 6; i++) acc[j][i] = 0ull;

    const f4u* wb = (const f4u*)(Ws + (h * 6) * (D_DIM / 2));

    for (int kt = 0; kt < NKT; kt++) {
        cpwait<1>();
        __syncthreads();

        u64* xs = (kt & 1) ? xs1 : xs0;
        const f4u* xrow0 = (const f4u*)(xs + (rid)       * XS_STRIDE);
        const f4u* xrow1 = (const f4u*)(xs + (rid + 64)  * XS_STRIDE);
        const f4u* xrow2 = (const f4u*)(xs + (rid + 128) * XS_STRIDE);
        const f4u* xrow3 = (const f4u*)(xs + (rid + 192) * XS_STRIDE);

#pragma unroll
        for (int kk2 = 0; kk2 < KT / 4; kk2++) {
            f4u xv0 = xrow0[kk2];
            f4u xv1 = xrow1[kk2];
            f4u xv2 = xrow2[kk2];
            f4u xv3 = xrow3[kk2];
#pragma unroll
            for (int i = 0; i < 6; i++) {
                f4u wv = wb[i * WTAG_F4U + kt * (KT / 4) + kk2];
                acc[0][i] = ffma2(xv0.lo, wv.lo, acc[0][i]);
                acc[0][i] = ffma2(xv0.hi, wv.hi, acc[0][i]);
                acc[1][i] = ffma2(xv1.lo, wv.lo, acc[1][i]);
                acc[1][i] = ffma2(xv1.hi, wv.hi, acc[1][i]);
                acc[2][i] = ffma2(xv2.lo, wv.lo, acc[2][i]);
                acc[2][i] = ffma2(xv2.hi, wv.hi, acc[2][i]);
                acc[3][i] = ffma2(xv3.lo, wv.lo, acc[3][i]);
                acc[3][i] = ffma2(xv3.hi, wv.hi, acc[3][i]);
            }
        }

        __syncthreads();
        if (kt + 2 < NKT) {
            uint32_t dst = (kt & 1) ? xsa1 : xsa0;
#pragma unroll
            for (int j = 0; j < 4; j++) {
                int idx = tid + j * 256;
                int row = idx >> 2;
                int c   = idx & 3;
                cpasync16(dst + row * 80 + c * 16,
                          x4g + (size_t)row * (D_DIM / 4) + (kt + 2) * 4 + c);
            }
            cpcommit();
        }
    }

    float bb[6], lbb[6], rbb[6];
#pragma unroll
    for (int i = 0; i < 6; i++) {
        int n = h * 6 + i;
        bb[i]  = bias[n];
        lbb[i] = lb[n];
        rbb[i] = rb[n];
    }
#pragma unroll
    for (int j = 0; j < 4; j++) {
        int r = rowg + rid + j * 64;
        int t = r & (T_LEN - 1);
        float v[6];
#pragma unroll
        for (int i = 0; i < 6; i++) {
            float s = lof(acc[j][i]) + hif(acc[j][i]) + bb[i];
            if (t == 0)         s += lbb[i];
            if (t == T_LEN - 1) s += rbb[i];
            v[i] = s;
        }
        float2* outp = (float2*)(potOut + (size_t)r * N_TAG + h * 6);
        outp[0] = make_float2(v[0], v[1]);
        outp[1] = make_float2(v[2], v[3]);
        outp[2] = make_float2(v[4], v[5]);
    }
}

// ---------------------------------------------------------------------------
// Viterbi (R15 proven) with the per-step WARPSYNC removed from the value
// warp's inner loop: the loop body is branch-free (converged warp, single
// instruction stream), so the warp's ring STS precedes its next-iteration
// LDS in LSU order — no intra-warp sync needed. Cross-warp visibility to
// the bp warps is provided by bar96 (BAR.SYNC drains pending STS).
// ---------------------------------------------------------------------------
#define CHUNK 64
#define NCHUNK (T_LEN / CHUNK)          // 16
#define CH_FLOATS (CHUNK * N_TAG)       // 1536 floats = 6144 B
#define BANK 16
#define NBANK (T_LEN / BANK)            // 64

// dynamic smem (bytes):
// potS [0,12288) | ring [12288,20480) | bp [20480,53248) (1024 rows x 32)
// cMap [53248,54784) | eArr [54784,54848) | lastTag [54848,54852)
#define VS_POT    0
#define VS_RING   12288
#define VS_BP     20480
#define VS_CMAP   53248
#define VS_EARR   54784
#define VS_LTAG   54848
#define VS_TOTAL  54912

extern __shared__ char vit_smem[];

__global__ void __launch_bounds__(128, 1)
viterbi_kernel(const float* __restrict__ pot,
               const float* __restrict__ trans,
               float* __restrict__ decodedOut) {
    float* potS = (float*)(vit_smem + VS_POT);       // [2][1536]
    float* ring = (float*)(vit_smem + VS_RING);      // [64][32]
    unsigned char* bp_s = (unsigned char*)(vit_smem + VS_BP);    // [1024][32]
    unsigned char* cMap = (unsigned char*)(vit_smem + VS_CMAP);  // [64][24]
    unsigned char* eArr = (unsigned char*)(vit_smem + VS_EARR);  // [64]
    int* lastTagS = (int*)(vit_smem + VS_LTAG);

    int b    = blockIdx.x;
    int tid  = threadIdx.x;
    int wid  = tid >> 5;
    int lane = tid & 31;
    int ln   = lane < N_TAG ? lane : (N_TAG - 1);

    if (wid == 3) return;   // spare warp (not in bar96 count)

    const float* potB = pot + (size_t)b * T_LEN * N_TAG;

    // identity row for t=0 (read only after bar96s -> visible)
    if (wid == 2) bp_s[0 * 32 + lane] = (unsigned char)ln;

    // tc packed in pairs: tc2[j] = (trans[2j][ln], trans[2j+1][ln])
    u64 tc2[12];
#pragma unroll
    for (int j = 0; j < 12; j++) {
        float t0 = trans[(2 * j) * N_TAG + ln];
        float t1 = trans[(2 * j + 1) * N_TAG + ln];
        tc2[j] = (u64)__float_as_uint(t0) | ((u64)__float_as_uint(t1) << 32);
    }

    if (wid == 0) {
        // ------------------- A: value warp -------------------
        uint32_t potS_addr = (uint32_t)__cvta_generic_to_shared(potS);

        // Prologue: chunks 0 and 1
#pragma unroll
        for (int j = 0; j < 12; j++)
            cpasync16(potS_addr + j * 512 + lane * 16, potB + j * 128 + lane * 4);
        cpcommit();
#pragma unroll
        for (int j = 0; j < 12; j++)
            cpasync16(potS_addr + 6144 + j * 512 + lane * 16,
                      potB + CH_FLOATS + j * 128 + lane * 4);
        cpcommit();
        cpwait<1>();
        __syncwarp();

        float alpha = potS[ln];         // t = 0
        ring[0 * 32 + lane] = alpha;    // slot 0
        __syncwarp();

        for (int k = 0; k < NBANK; k++) {
            int tstart = (k == 0) ? 1 : 16 * k;
            int tend   = 16 * k + 16;
#pragma unroll 4
            for (int t = tstart; t < tend; t++) {
                float pcur = potS[((t >> 6) & 1) * CH_FLOATS
                                  + (t & 63) * N_TAG + ln];

                const f4u* ap = (const f4u*)(ring + ((t - 1) & 63) * 32);
                float s[N_TAG];
#pragma unroll
                for (int q = 0; q < 6; q++) {
                    f4u a = ap[q];
                    u64 sa = fadd2(a.lo, tc2[2 * q]);
                    u64 sb = fadd2(a.hi, tc2[2 * q + 1]);
                    s[4 * q + 0] = lof(sa); s[4 * q + 1] = hif(sa);
                    s[4 * q + 2] = lof(sb); s[4 * q + 3] = hif(sb);
                }
                // value-only tournament (same pairing as bp warps)
#pragma unroll
                for (int st = 1; st < N_TAG; st <<= 1) {
#pragma unroll
                    for (int i = 0; i + st < N_TAG; i += 2 * st)
                        s[i] = fmaxf(s[i], s[i + st]);
                }
                alpha = s[0] + pcur;
                ring[(t & 63) * 32 + lane] = alpha;
                // no per-step __syncwarp: branch-free converged warp; its own
                // STS precedes next-iter LDS in LSU order.
            }
            // end of chunk c = k>>2: refill c+2, ensure c+1 landed
            if ((k & 3) == 3) {
                int c = k >> 2;
                if (c + 2 < NCHUNK) {
                    uint32_t dst = potS_addr + (c & 1) * 6144;
                    const float* src = potB + (size_t)(c + 2) * CH_FLOATS;
#pragma unroll
                    for (int j = 0; j < 12; j++)
                        cpasync16(dst + j * 512 + lane * 16,
                                  src + j * 128 + lane * 4);
                    cpcommit();
                    cpwait<1>();
                } else {
                    cpwait<0>();
                }
                __syncwarp();
            }
            bar96();    // release bank k to bp warps (drains STS)
        }

        // last_tag = first-occurrence argmax over lanes 0..23
        float bv = __shfl_sync(0xffffffffu, alpha, 0);
        int   bt = 0;
#pragma unroll
        for (int m = 1; m < N_TAG; m++) {
            float v = __shfl_sync(0xffffffffu, alpha, m);
            if (v > bv) { bv = v; bt = m; }
        }
        if (lane == 0) lastTagS[0] = bt;
        bar96();        // bp warps finished last bank; lastTag visible
    } else {
        // ------------------- B0/B1: backpointer warps -------------------
        int w = wid - 1;    // 0 or 1: parity split of steps within a bank
        for (int k = 0; k < NBANK; k++) {
            bar96();        // bank k alphas ready
            int tstart = ((k == 0) ? 1 : 16 * k) + w;
            int tend   = 16 * k + 16;
            for (int t = tstart; t < tend; t += 2) {
                const f4u* ap = (const f4u*)(ring + ((t - 1) & 63) * 32);
                float s[N_TAG];
                int   idx[N_TAG];
#pragma unroll
                for (int q = 0; q < 6; q++) {
                    f4u a = ap[q];
                    u64 sa = fadd2(a.lo, tc2[2 * q]);
                    u64 sb = fadd2(a.hi, tc2[2 * q + 1]);
                    s[4 * q + 0] = lof(sa); s[4 * q + 1] = hif(sa);
                    s[4 * q + 2] = lof(sb); s[4 * q + 3] = hif(sb);
                }
#pragma unroll
                for (int m = 0; m < N_TAG; m++) idx[m] = m;

                // (val,idx) tournament; strict '>' keeps first-occurrence ties
#define VCMP(i, j) { bool g = s[j] > s[i];          \
                     idx[i] = g ? idx[j] : idx[i];   \
                     s[i] = fmaxf(s[i], s[j]); }
#pragma unroll
                for (int st = 1; st < N_TAG; st <<= 1) {
#pragma unroll
                    for (int i = 0; i + st < N_TAG; i += 2 * st) VCMP(i, i + st)
                }
#undef VCMP
                bp_s[t * 32 + lane] = (unsigned char)idx[0];   // row = t
            }
        }
        bar96();    // signals bp complete
    }

    // =============== Parallel backtrace (all 96 threads) ===============
    int tt = wid * 32 + lane;   // 0..95

    // Phase 1: per-bank composed maps (16 chains/thread, ILP)
    {
        int xReg[16];
        int bankT[16];
#pragma unroll
        for (int j = 0; j < 16; j++) {
            int p = tt + 96 * j;        // 0..1535
            bankT[j] = (p / 24) * 16;   // 16*bank
            xReg[j] = p % 24;
        }
        for (int i = 15; i >= 0; i--) {
#pragma unroll
            for (int j = 0; j < 16; j++)
                xReg[j] = bp_s[(bankT[j] + i) * 32 + xReg[j]];
        }
#pragma unroll
        for (int j = 0; j < 16; j++)
            cMap[tt + 96 * j] = (unsigned char)xReg[j];
    }
    bar96();

    // Phase 2: boundary tags eArr[k] = state at t=16k+15
    if (tt == 0) {
        int e = lastTagS[0];
        eArr[63] = (unsigned char)e;
        for (int k = 63; k >= 1; k--) {
            e = cMap[k * 24 + e];
            eArr[k - 1] = (unsigned char)e;
        }
    }
    bar96();

    // Phase 3: reconstruct decoded per bank (threads 0..63)
    if (tt < 64) {
        int k = tt;
        int xx = eArr[k];               // state at t=16k+15
        float* dec = decodedOut + (size_t)b * T_LEN;
        if (k == 63) dec[1023] = (float)xx;
        for (int t = 16 * k + 15; t >= 16 * k; t--) {
            xx = bp_s[t * 32 + xx];
            if (t > 0) dec[t - 1] = (float)xx;
        }
    }
}

// ---------------------------------------------------------------------------
__global__ void tail_kernel(const float* __restrict__ trans,
                            float* __restrict__ out) {
    int i = threadIdx.x;
    if (i < B_SZ)          out[OFF_LENS + i]  = (float)T_LEN;
    if (i < N_TAG * N_TAG) out[OFF_TRANS + i] = trans[i];
}

// ---------------------------------------------------------------------------
extern "C" void kernel_launch(void* const* d_in, const int* in_sizes, int n_in,
                              void* d_out, int out_size) {
    const float* x     = (const float*)d_in[0];
    const float* W     = (const float*)d_in[1];
    const float* bias  = (const float*)d_in[2];
    const float* trans = (const float*)d_in[3];
    const float* lb    = (const float*)d_in[4];
    const float* rb    = (const float*)d_in[5];

    float* out = (float*)d_out;
    float* pot = out + OFF_POT;

    int gemm_smem = (N_TAG * (D_DIM / 2) + 2 * XS_U64) * 8;   // 90112
    cudaFuncSetAttribute(gemm_pot_kernel,
                         cudaFuncAttributeMaxDynamicSharedMemorySize, gemm_smem);
    cudaFuncSetAttribute(viterbi_kernel,
                         cudaFuncAttributeMaxDynamicSharedMemorySize, VS_TOTAL);

    gemm_pot_kernel<<<(B_SZ * T_LEN) / ROWS_BLK, 256, gemm_smem>>>(
        x, W, bias, lb, rb, pot);
    tail_kernel<<<1, 640>>>(trans, out);
    viterbi_kernel<<<B_SZ, 128, VS_TOTAL>>>(pot, trans, out);
}